// round 6
// baseline (speedup 1.0000x reference)
#include <cuda_runtime.h>
#include <cuda_fp16.h>
#include <cstdint>

// SGConv K=2: h = P (P x), P = D^-1/2 (A + I) D^-1/2, deg over dst (+ self loop).
// z = dis .* h form: out[d] = dis[d]*(z[d] + sum_{s in N(d)} z[s]); CSR stores only
// src. z kept in fp16, SPLIT-PLANE layout: plane A = features 0..63 (32 u32/node,
// one 128B line), plane B = features 64..95 (16 u32/node, one 64B half-line) ->
// 6 fully-utilized sectors per edge gather. dtype (int32 vs int64 edge_index)
// detected per-warp via ballot on odd words of src (no separate kernel).
// Launches: memset, degree(+rank), scan(prefix+dis), scatter(+z0 scale), hop1, hop2.

#define N_NODES 50000
#define N_EDGES 800000
#define N_FEAT  96
#define PA_U    32                            // plane-A u32 per node (feat 0..63)
#define PB_U    16                            // plane-B u32 per node (feat 64..95)
#define ROW_F2  (N_FEAT / 2)                  // 48 float2 per fp32 row
#define SCAN_B  1024
#define N_CHUNK ((N_NODES + SCAN_B - 1) / SCAN_B)   // 49

// ---------------- device scratch (allocation-free rule: __device__ globals) ----
__device__ int   g_counts[N_NODES];           // in-degree (dst)
__device__ int   g_rowptr[N_NODES + 1];       // CSR row pointers (by dst)
__device__ float g_dis[N_NODES];              // (deg+1)^-1/2
__device__ int   g_pos[N_EDGES];              // within-row rank of edge e
__device__ int   g_col[N_EDGES];              // src per CSR slot
__device__ __align__(128) unsigned int g_z0a[(size_t)N_NODES * PA_U];
__device__ __align__(128) unsigned int g_z0b[(size_t)N_NODES * PB_U];
__device__ __align__(128) unsigned int g_z1a[(size_t)N_NODES * PA_U];
__device__ __align__(128) unsigned int g_z1b[(size_t)N_NODES * PB_U];

// ---------------- per-warp dtype detection -------------------------------------
// Odd 32-bit words of src (int64 view) are all 0 iff int64 (values < 50000).
// For int32 data those words are src values: P(32 consecutive all zero) ~ 0.
// Reads stay within the first 1.6M u32 words = valid for both dtypes.
__device__ __forceinline__ bool warp_is64(const void* ei, int ebase, int lane) {
    int e = ebase + lane;
    if (e >= N_EDGES) e = N_EDGES - 1;
    unsigned int v = ((const unsigned int*)ei)[2 * e + 1];
    return __all_sync(0xFFFFFFFFu, v == 0);
}
__device__ __forceinline__ int edge_src(const void* ei, int e, bool is64) {
    return is64 ? (int)((const long long*)ei)[e] : ((const int*)ei)[e];
}
__device__ __forceinline__ int edge_dst(const void* ei, int e, bool is64) {
    return is64 ? (int)((const long long*)ei)[N_EDGES + e]
                : ((const int*)ei)[N_EDGES + e];
}

// ---------------- degree + edge rank (N_EDGES % 256 == 0: all warps full) ------
__global__ void degree_kernel(const void* __restrict__ ei) {
    int e = blockIdx.x * blockDim.x + threadIdx.x;
    if (e >= N_EDGES) return;
    const int lane = threadIdx.x & 31;
    bool is64 = warp_is64(ei, e - lane, lane);
    int d = edge_dst(ei, e, is64);
    g_pos[e] = atomicAdd(&g_counts[d], 1);
}

// ---------------- single-kernel scan: prefix + dis + rowptr ---------------------
// Each block sums ALL counts before its chunk (coalesced strided loads), then
// block-scans its own 1024 counts. Also emits dis.
__global__ void __launch_bounds__(SCAN_B) scan_kernel() {
    const int tid = threadIdx.x, lane = tid & 31, wid = tid >> 5;
    const int b = blockIdx.x;
    const int i = b * SCAN_B + tid;

    __shared__ int wred[32];
    __shared__ int s_pre;
    __shared__ int wscan[32];

    // prefix over chunks [0, b)
    int pre = 0;
    const int lim = b * SCAN_B;
    for (int j = tid; j < lim; j += SCAN_B) pre += g_counts[j];
    int v = pre;
    #pragma unroll
    for (int off = 16; off > 0; off >>= 1) v += __shfl_down_sync(0xFFFFFFFFu, v, off);
    if (lane == 0) wred[wid] = v;
    __syncthreads();
    if (wid == 0) {
        int s = wred[lane];
        #pragma unroll
        for (int off = 16; off > 0; off >>= 1) s += __shfl_down_sync(0xFFFFFFFFu, s, off);
        if (lane == 0) s_pre = s;
    }

    // own chunk: dis + inclusive scan
    int c = 0;
    if (i < N_NODES) {
        c = g_counts[i];
        g_dis[i] = rsqrtf((float)(c + 1));   // +1 self loop
    }
    int incl = c;
    #pragma unroll
    for (int off = 1; off < 32; off <<= 1) {
        int t = __shfl_up_sync(0xFFFFFFFFu, incl, off);
        if (lane >= off) incl += t;
    }
    if (lane == 31) wscan[wid] = incl;
    __syncthreads();
    if (wid == 0) {
        int s = wscan[lane];
        #pragma unroll
        for (int off = 1; off < 32; off <<= 1) {
            int t = __shfl_up_sync(0xFFFFFFFFu, s, off);
            if (lane >= off) s += t;
        }
        wscan[lane] = s;
    }
    __syncthreads();

    if (i < N_NODES)
        g_rowptr[i + 1] = s_pre + (wid > 0 ? wscan[wid - 1] : 0) + incl;
    if (b == 0 && tid == 0) g_rowptr[0] = 0;
}

// ---------------- scatter (atomic-free) + z0 scale ------------------------------
__global__ void __launch_bounds__(256) scatter_scale_kernel(const void* __restrict__ ei,
                                                            const float* __restrict__ x) {
    int idx = blockIdx.x * blockDim.x + threadIdx.x;
    const int lane = threadIdx.x & 31;

    if (idx < N_EDGES) {   // N_EDGES % 32 == 0: whole warps take this branch
        bool is64 = warp_is64(ei, idx - lane, lane);
        int s = edge_src(ei, idx, is64);
        int d = edge_dst(ei, idx, is64);
        g_col[g_rowptr[d] + g_pos[idx]] = s;
    }

    // z0 = half(dis .* x), split planes. 2.4M float2 elements, grid-stride.
    const int TOT = N_NODES * ROW_F2;
    const int stride = gridDim.x * blockDim.x;
    for (int i = idx; i < TOT; i += stride) {
        int node = i / ROW_F2;
        int j    = i - node * ROW_F2;
        float sdis = g_dis[node];
        float2 v = ((const float2*)x)[i];
        __half2 h = __floats2half2_rn(sdis * v.x, sdis * v.y);
        unsigned int bits = *(unsigned int*)&h;
        if (j < PA_U) g_z0a[(size_t)node * PA_U + j] = bits;
        else          g_z0b[(size_t)node * PB_U + (j - PA_U)] = bits;
    }
}

// ---------------- hop: warp/node, split-plane fp16 gather, fp32 accumulate ------
// Lane L: plane-A u32[L] -> features (2L, 2L+1); lanes<16: plane-B u32[L] ->
// features (64+2L, 65+2L). FIRST: z-space fp16 out (*dis^2); else fp32 (*dis).
template <bool FIRST>
__global__ void __launch_bounds__(256) hop_kernel(const unsigned int* __restrict__ za,
                                                  const unsigned int* __restrict__ zb,
                                                  unsigned int* __restrict__ oa,
                                                  unsigned int* __restrict__ ob,
                                                  float* __restrict__ of) {
    const int node = blockIdx.x * (blockDim.x >> 5) + (threadIdx.x >> 5);
    if (node >= N_NODES) return;
    const int lane = threadIdx.x & 31;
    const bool lo = (lane < PB_U);

    float a0, a1, a2 = 0.f, a3 = 0.f;
    {
        unsigned int u = za[(size_t)node * PA_U + lane];
        float2 f = __half22float2(*(__half2*)&u);
        a0 = f.x; a1 = f.y;
        if (lo) {
            unsigned int w = zb[(size_t)node * PB_U + lane];
            float2 g = __half22float2(*(__half2*)&w);
            a2 = g.x; a3 = g.y;
        }
    }

    int e = g_rowptr[node];
    const int end = g_rowptr[node + 1];

    for (; e + 3 < end; e += 4) {
        int s0 = g_col[e], s1 = g_col[e + 1], s2 = g_col[e + 2], s3 = g_col[e + 3];
        unsigned int q0 = za[(size_t)s0 * PA_U + lane];
        unsigned int q1 = za[(size_t)s1 * PA_U + lane];
        unsigned int q2 = za[(size_t)s2 * PA_U + lane];
        unsigned int q3 = za[(size_t)s3 * PA_U + lane];
        unsigned int p0 = 0, p1 = 0, p2 = 0, p3 = 0;
        if (lo) {
            p0 = zb[(size_t)s0 * PB_U + lane];
            p1 = zb[(size_t)s1 * PB_U + lane];
            p2 = zb[(size_t)s2 * PB_U + lane];
            p3 = zb[(size_t)s3 * PB_U + lane];
        }
        float2 t;
        t = __half22float2(*(__half2*)&q0); a0 += t.x; a1 += t.y;
        t = __half22float2(*(__half2*)&q1); a0 += t.x; a1 += t.y;
        t = __half22float2(*(__half2*)&q2); a0 += t.x; a1 += t.y;
        t = __half22float2(*(__half2*)&q3); a0 += t.x; a1 += t.y;
        t = __half22float2(*(__half2*)&p0); a2 += t.x; a3 += t.y;
        t = __half22float2(*(__half2*)&p1); a2 += t.x; a3 += t.y;
        t = __half22float2(*(__half2*)&p2); a2 += t.x; a3 += t.y;
        t = __half22float2(*(__half2*)&p3); a2 += t.x; a3 += t.y;
    }
    for (; e < end; e++) {
        int s = g_col[e];
        unsigned int q = za[(size_t)s * PA_U + lane];
        float2 t = __half22float2(*(__half2*)&q);
        a0 += t.x; a1 += t.y;
        if (lo) {
            unsigned int p = zb[(size_t)s * PB_U + lane];
            float2 u = __half22float2(*(__half2*)&p);
            a2 += u.x; a3 += u.y;
        }
    }

    float sc = g_dis[node];
    if (FIRST) {
        sc = sc * sc;
        __half2 h01 = __floats2half2_rn(sc * a0, sc * a1);
        oa[(size_t)node * PA_U + lane] = *(unsigned int*)&h01;
        if (lo) {
            __half2 h23 = __floats2half2_rn(sc * a2, sc * a3);
            ob[(size_t)node * PB_U + lane] = *(unsigned int*)&h23;
        }
    } else {
        float2* ho = (float2*)of + (size_t)node * ROW_F2;
        ho[lane] = make_float2(sc * a0, sc * a1);
        if (lo) ho[PA_U + lane] = make_float2(sc * a2, sc * a3);
    }
}

// ---------------- launch --------------------------------------------------------
extern "C" void kernel_launch(void* const* d_in, const int* in_sizes, int n_in,
                              void* d_out, int out_size) {
    const float* x  = (const float*)d_in[0];
    const void*  ei = d_in[1];

    int* cnt = nullptr;
    unsigned int *z0a, *z0b, *z1a, *z1b;
    cudaGetSymbolAddress((void**)&cnt, g_counts);
    cudaGetSymbolAddress((void**)&z0a, g_z0a);
    cudaGetSymbolAddress((void**)&z0b, g_z0b);
    cudaGetSymbolAddress((void**)&z1a, g_z1a);
    cudaGetSymbolAddress((void**)&z1b, g_z1b);

    const int TB = 256;
    cudaMemsetAsync(cnt, 0, N_NODES * sizeof(int));
    degree_kernel<<<N_EDGES / TB, TB>>>(ei);                 // 3125 full blocks
    scan_kernel<<<N_CHUNK, SCAN_B>>>();
    const int TOT = N_NODES * ROW_F2;                        // 2.4M
    scatter_scale_kernel<<<(TOT + TB - 1) / TB, TB>>>(ei, x);

    const int warps_per_block = TB / 32;
    const int hop_grid = (N_NODES + warps_per_block - 1) / warps_per_block;
    hop_kernel<true ><<<hop_grid, TB>>>(z0a, z0b, z1a, z1b, nullptr);
    hop_kernel<false><<<hop_grid, TB>>>(z1a, z1b, nullptr, nullptr, (float*)d_out);
}

// round 7
// speedup vs baseline: 1.2632x; 1.2632x over previous
#include <cuda_runtime.h>
#include <cuda_fp16.h>
#include <cstdint>

// SGConv K=2: h = P (P x), P = D^-1/2 (A + I) D^-1/2, deg over dst (+ self loop).
// z = dis .* h form: out[d] = dis[d]*(z[d] + sum_{s in N(d)} z[s]); CSR stores only
// src. z kept in fp16, ONE contiguous 192B row per node (48 u32 = 24 uint2).
// Hop is ISSUE-bound (ncu R6: issue=71%, alu=48%, L2=19.5%) -> minimize
// warp-instructions per edge: single LDG.64 per edge (lane<24 owns 4 features),
// pure int32 index math (one IMAD per gather), 4-edge unroll, fp32 accumulate.
// Launches: memset, degree(+rank), scan(prefix+dis), scatter(+z0 scale), hop1, hop2.

#define N_NODES 50000
#define N_EDGES 800000
#define N_FEAT  96
#define ROW_U   48                            // u32 per fp16 row
#define ROW_V   24                            // uint2 per fp16 row
#define SCAN_B  1024
#define N_CHUNK ((N_NODES + SCAN_B - 1) / SCAN_B)   // 49

// ---------------- device scratch (allocation-free rule: __device__ globals) ----
__device__ int   g_counts[N_NODES];           // in-degree (dst)
__device__ int   g_rowptr[N_NODES + 1];       // CSR row pointers (by dst)
__device__ float g_dis[N_NODES];              // (deg+1)^-1/2
__device__ int   g_pos[N_EDGES];              // within-row rank of edge e
__device__ int   g_col[N_EDGES];              // src per CSR slot
__device__ __align__(128) uint2 g_z0h[(size_t)N_NODES * ROW_V];
__device__ __align__(128) uint2 g_z1h[(size_t)N_NODES * ROW_V];

// ---------------- per-warp dtype detection -------------------------------------
// Odd 32-bit words of src (int64 view) are all 0 iff int64 (values < 50000).
// For int32 data those words are src values: P(32 consecutive all zero) ~ 0.
__device__ __forceinline__ bool warp_is64(const void* ei, int ebase, int lane) {
    int e = ebase + lane;
    if (e >= N_EDGES) e = N_EDGES - 1;
    unsigned int v = ((const unsigned int*)ei)[2 * e + 1];
    return __all_sync(0xFFFFFFFFu, v == 0);
}
__device__ __forceinline__ int edge_src(const void* ei, int e, bool is64) {
    return is64 ? (int)((const long long*)ei)[e] : ((const int*)ei)[e];
}
__device__ __forceinline__ int edge_dst(const void* ei, int e, bool is64) {
    return is64 ? (int)((const long long*)ei)[N_EDGES + e]
                : ((const int*)ei)[N_EDGES + e];
}

// ---------------- degree + edge rank -------------------------------------------
__global__ void degree_kernel(const void* __restrict__ ei) {
    int e = blockIdx.x * blockDim.x + threadIdx.x;
    if (e >= N_EDGES) return;
    const int lane = threadIdx.x & 31;
    bool is64 = warp_is64(ei, e - lane, lane);
    int d = edge_dst(ei, e, is64);
    g_pos[e] = atomicAdd(&g_counts[d], 1);
}

// ---------------- single-kernel scan: prefix + dis + rowptr ---------------------
__global__ void __launch_bounds__(SCAN_B) scan_kernel() {
    const int tid = threadIdx.x, lane = tid & 31, wid = tid >> 5;
    const int b = blockIdx.x;
    const int i = b * SCAN_B + tid;

    __shared__ int wred[32];
    __shared__ int s_pre;
    __shared__ int wscan[32];

    // prefix over chunks [0, b)
    int pre = 0;
    const int lim = b * SCAN_B;
    for (int j = tid; j < lim; j += SCAN_B) pre += g_counts[j];
    int v = pre;
    #pragma unroll
    for (int off = 16; off > 0; off >>= 1) v += __shfl_down_sync(0xFFFFFFFFu, v, off);
    if (lane == 0) wred[wid] = v;
    __syncthreads();
    if (wid == 0) {
        int s = wred[lane];
        #pragma unroll
        for (int off = 16; off > 0; off >>= 1) s += __shfl_down_sync(0xFFFFFFFFu, s, off);
        if (lane == 0) s_pre = s;
    }

    int c = 0;
    if (i < N_NODES) {
        c = g_counts[i];
        g_dis[i] = rsqrtf((float)(c + 1));   // +1 self loop
    }
    int incl = c;
    #pragma unroll
    for (int off = 1; off < 32; off <<= 1) {
        int t = __shfl_up_sync(0xFFFFFFFFu, incl, off);
        if (lane >= off) incl += t;
    }
    if (lane == 31) wscan[wid] = incl;
    __syncthreads();
    if (wid == 0) {
        int s = wscan[lane];
        #pragma unroll
        for (int off = 1; off < 32; off <<= 1) {
            int t = __shfl_up_sync(0xFFFFFFFFu, s, off);
            if (lane >= off) s += t;
        }
        wscan[lane] = s;
    }
    __syncthreads();

    if (i < N_NODES)
        g_rowptr[i + 1] = s_pre + (wid > 0 ? wscan[wid - 1] : 0) + incl;
    if (b == 0 && tid == 0) g_rowptr[0] = 0;
}

// ---------------- scatter (atomic-free) + z0 scale ------------------------------
__global__ void __launch_bounds__(256) scatter_scale_kernel(const void* __restrict__ ei,
                                                            const float* __restrict__ x) {
    int idx = blockIdx.x * blockDim.x + threadIdx.x;
    const int lane = threadIdx.x & 31;

    if (idx < N_EDGES) {   // N_EDGES % 32 == 0: whole warps take this branch
        bool is64 = warp_is64(ei, idx - lane, lane);
        int s = edge_src(ei, idx, is64);
        int d = edge_dst(ei, idx, is64);
        g_col[g_rowptr[d] + g_pos[idx]] = s;
    }

    // z0 = half(dis .* x): one u32 (half2) per iteration, grid-stride.
    const int TOT = N_NODES * ROW_U;
    const int stride = gridDim.x * blockDim.x;
    unsigned int* z0 = (unsigned int*)g_z0h;
    for (int i = idx; i < TOT; i += stride) {
        int node = i / ROW_U;
        float sdis = g_dis[node];
        float2 v = ((const float2*)x)[i];
        __half2 h = __floats2half2_rn(sdis * v.x, sdis * v.y);
        z0[i] = *(unsigned int*)&h;
    }
}

// ---------------- hop: warp/node, LDG.64 fp16 gather, fp32 accumulate -----------
// Lane L (<24) owns features 4L..4L+3 via uint2. int32 index math only.
// FIRST: z-space fp16 out (*dis^2); else final fp32 out (*dis).
template <bool FIRST>
__global__ void __launch_bounds__(256) hop_kernel(const uint2* __restrict__ zin,
                                                  uint2* __restrict__ zout,
                                                  float4* __restrict__ fout) {
    const int node = blockIdx.x * (blockDim.x >> 5) + (threadIdx.x >> 5);
    if (node >= N_NODES) return;
    const int lane = threadIdx.x & 31;
    const bool act = (lane < ROW_V);

    float a0 = 0.f, a1 = 0.f, a2 = 0.f, a3 = 0.f;
    if (act) {
        uint2 u = zin[node * ROW_V + lane];
        float2 f0 = __half22float2(*(__half2*)&u.x);
        float2 f1 = __half22float2(*(__half2*)&u.y);
        a0 = f0.x; a1 = f0.y; a2 = f1.x; a3 = f1.y;
    }

    int e = g_rowptr[node];
    const int end = g_rowptr[node + 1];

    for (; e + 3 < end; e += 4) {
        int i0 = g_col[e]     * ROW_V + lane;
        int i1 = g_col[e + 1] * ROW_V + lane;
        int i2 = g_col[e + 2] * ROW_V + lane;
        int i3 = g_col[e + 3] * ROW_V + lane;
        if (act) {
            uint2 v0 = zin[i0];
            uint2 v1 = zin[i1];
            uint2 v2 = zin[i2];
            uint2 v3 = zin[i3];
            float2 t;
            t = __half22float2(*(__half2*)&v0.x); a0 += t.x; a1 += t.y;
            t = __half22float2(*(__half2*)&v0.y); a2 += t.x; a3 += t.y;
            t = __half22float2(*(__half2*)&v1.x); a0 += t.x; a1 += t.y;
            t = __half22float2(*(__half2*)&v1.y); a2 += t.x; a3 += t.y;
            t = __half22float2(*(__half2*)&v2.x); a0 += t.x; a1 += t.y;
            t = __half22float2(*(__half2*)&v2.y); a2 += t.x; a3 += t.y;
            t = __half22float2(*(__half2*)&v3.x); a0 += t.x; a1 += t.y;
            t = __half22float2(*(__half2*)&v3.y); a2 += t.x; a3 += t.y;
        }
    }
    for (; e < end; e++) {
        int i = g_col[e] * ROW_V + lane;
        if (act) {
            uint2 v = zin[i];
            float2 t;
            t = __half22float2(*(__half2*)&v.x); a0 += t.x; a1 += t.y;
            t = __half22float2(*(__half2*)&v.y); a2 += t.x; a3 += t.y;
        }
    }

    float sc = g_dis[node];
    if (FIRST) {
        sc = sc * sc;
        if (act) {
            __half2 h01 = __floats2half2_rn(sc * a0, sc * a1);
            __half2 h23 = __floats2half2_rn(sc * a2, sc * a3);
            uint2 o;
            o.x = *(unsigned int*)&h01;
            o.y = *(unsigned int*)&h23;
            zout[node * ROW_V + lane] = o;
        }
    } else {
        if (act)
            fout[node * ROW_V + lane] =
                make_float4(sc * a0, sc * a1, sc * a2, sc * a3);
    }
}

// ---------------- launch --------------------------------------------------------
extern "C" void kernel_launch(void* const* d_in, const int* in_sizes, int n_in,
                              void* d_out, int out_size) {
    const float* x  = (const float*)d_in[0];
    const void*  ei = d_in[1];

    int* cnt = nullptr; uint2 *z0, *z1;
    cudaGetSymbolAddress((void**)&cnt, g_counts);
    cudaGetSymbolAddress((void**)&z0, g_z0h);
    cudaGetSymbolAddress((void**)&z1, g_z1h);

    const int TB = 256;
    cudaMemsetAsync(cnt, 0, N_NODES * sizeof(int));
    degree_kernel<<<N_EDGES / TB, TB>>>(ei);
    scan_kernel<<<N_CHUNK, SCAN_B>>>();
    const int TOT = N_NODES * ROW_U;
    scatter_scale_kernel<<<(TOT + TB - 1) / TB, TB>>>(ei, x);

    const int warps_per_block = TB / 32;
    const int hop_grid = (N_NODES + warps_per_block - 1) / warps_per_block;
    hop_kernel<true ><<<hop_grid, TB>>>(z0, z1, nullptr);
    hop_kernel<false><<<hop_grid, TB>>>(z1, nullptr, (float4*)d_out);
}